// round 2
// baseline (speedup 1.0000x reference)
#include <cuda_runtime.h>

// ---------------- problem constants ----------------
#define NP 50000
#define NTOP 256
#define BATCH 1024
#define NTOT (NP * NTOP)          // 12,800,000
#define HALF_X (NTOT / 2)         // 6,400,000
#define BT (BATCH * NTOP)         // 262,144
#define HALF_I (BT / 2)           // 131,072
#define K1_BLOCKS (HALF_X / 256)  // 25,000
#define K3_BLOCKS (HALF_I / 256)  // 512

// GEMM tiling
#define BBM 128
#define BBN 128
#define KC 16
#define NTILES 391                // ceil(50000/128)

// ---------------- scratch (static device globals; no allocation) ----------------
__device__ float g_X[NTOT];                 // x sample -> overwritten with p
__device__ float g_Pi[BT];                  // xi sample -> overwritten with pi
__device__ float g_sv[NP];
__device__ float g_rv[NP];                  // 1/(1-sv)
__device__ float g_su[BATCH];
__device__ float g_ru[BATCH];
__device__ float g_partial[BATCH * NTILES]; // per (b, ntile) sum of exp(d)
__device__ float g_dj[BATCH];
__device__ float g_kldb[BATCH];
__device__ float g_rp[K1_BLOCKS];           // analytic KL partials

// ---------------- Threefry-2x32 (exact JAX semantics) ----------------
__host__ __device__ __forceinline__ void tf2x32(unsigned int k0, unsigned int k1,
                                                unsigned int c0, unsigned int c1,
                                                unsigned int& o0, unsigned int& o1) {
  unsigned int ks2 = k0 ^ k1 ^ 0x1BD11BDAu;
  unsigned int x0 = c0 + k0, x1 = c1 + k1;
#define TF_R(d) { x0 += x1; x1 = (x1 << (d)) | (x1 >> (32 - (d))); x1 ^= x0; }
  TF_R(13) TF_R(15) TF_R(26) TF_R(6)   x0 += k1;  x1 += ks2 + 1u;
  TF_R(17) TF_R(29) TF_R(16) TF_R(24)  x0 += ks2; x1 += k0 + 2u;
  TF_R(13) TF_R(15) TF_R(26) TF_R(6)   x0 += k0;  x1 += k1 + 3u;
  TF_R(17) TF_R(29) TF_R(16) TF_R(24)  x0 += k1;  x1 += ks2 + 4u;
  TF_R(13) TF_R(15) TF_R(26) TF_R(6)   x0 += ks2; x1 += k0 + 5u;
#undef TF_R
  o0 = x0; o1 = x1;
}

__device__ __forceinline__ float bits_to_normal(unsigned int bits) {
  // JAX: f = bitcast(bits>>9 | 0x3f800000) - 1 in [0,1);
  //      u = max(lo, f*(1 - lo) + lo) with lo = nextafter(-1,0); (1-lo) rounds to 2.0f
  float f = __uint_as_float((bits >> 9) | 0x3f800000u) - 1.0f;
  float lo = __uint_as_float(0xBF7FFFFFu);  // -0.99999994
  float u = fmaxf(lo, fmaf(f, 2.0f, lo));
  return 1.41421356237f * erfinvf(u);       // sqrt(2) rounds to 0x3FB504F3
}

// ---------------- block reduce (256 threads, deterministic, broadcast) ----------------
__device__ __forceinline__ float blockReduce256(float v, volatile float* sh) {
#pragma unroll
  for (int o = 16; o > 0; o >>= 1) v += __shfl_down_sync(0xffffffffu, v, o);
  int lane = threadIdx.x & 31, w = threadIdx.x >> 5;
  if (lane == 0) sh[w] = v;
  __syncthreads();
  if (w == 0) {
    float r = (lane < 8) ? sh[lane] : 0.f;
#pragma unroll
    for (int o = 4; o > 0; o >>= 1) r += __shfl_down_sync(0xffffffffu, r, o);
    if (lane == 0) sh[8] = r;
  }
  __syncthreads();
  float out = sh[8];
  __syncthreads();
  return out;
}

// ---------------- K1: full embedding sample + analytic KL partials ----------------
__global__ __launch_bounds__(256) void k1_sample_x(const float* __restrict__ mu,
                                                   const float* __restrict__ lv,
                                                   unsigned int kx0, unsigned int kx1) {
  int g = blockIdx.x * 256 + threadIdx.x;   // grid sized exactly HALF_X/256
  unsigned int b0, b1;
  tf2x32(kx0, kx1, (unsigned int)g, (unsigned int)(g + HALF_X), b0, b1);
  float local = 0.f;
  {
    float m = mu[g], l = lv[g];
    g_X[g] = fmaf(bits_to_normal(b0), expf(0.5f * l), m);
    local += 1.0f + l - m * m - expf(l);
  }
  {
    int f = g + HALF_X;
    float m = mu[f], l = lv[f];
    g_X[f] = fmaf(bits_to_normal(b1), expf(0.5f * l), m);
    local += 1.0f + l - m * m - expf(l);
  }
  __shared__ float sh[16];
  float s = blockReduce256(local, sh);
  if (threadIdx.x == 0) g_rp[blockIdx.x] = s;
}

// ---------------- K3: batch sample with gather ----------------
__global__ __launch_bounds__(256) void k3_sample_xi(const float* __restrict__ mu,
                                                    const float* __restrict__ lv,
                                                    const int* __restrict__ iidx,
                                                    unsigned int ki0, unsigned int ki1) {
  int g = blockIdx.x * 256 + threadIdx.x;
  unsigned int b0, b1;
  tf2x32(ki0, ki1, (unsigned int)g, (unsigned int)(g + HALF_I), b0, b1);
#pragma unroll
  for (int h = 0; h < 2; h++) {
    int f = g + h * HALF_I;
    unsigned int bits = h ? b1 : b0;
    int row = f >> 8, col = f & 255;
    int a = iidx[row] * NTOP + col;
    float m = mu[a], l = lv[a];
    g_Pi[f] = fmaf(bits_to_normal(bits), expf(0.5f * l), m);
  }
}

// ---------------- K2/K4: double Poincare transform, in place ----------------
__global__ __launch_bounds__(256) void k_transform(int is_batch) {
  float* X = is_batch ? g_Pi : g_X;
  float* svout = is_batch ? g_su : g_sv;
  float* rvout = is_batch ? g_ru : g_rv;
  int row = blockIdx.x;
  int t = threadIdx.x;
  __shared__ float sh[16];
  float x = X[row * NTOP + t];
  float sx = blockReduce256(x * x, sh);
  float s1 = 1.f + sqrtf(1.f + sx);
  float y = x / s1;
  float sy = blockReduce256(y * y, sh);
  float s2 = 1.f + sqrtf(1.f + sy);
  float p = y / s2;
  X[row * NTOP + t] = p;
  float sp = blockReduce256(p * p, sh);
  if (t == 0) {
    float sv = fminf(fmaxf(sp, 0.f), 1.f - 1e-5f);
    svout[row] = sv;
    rvout[row] = 1.f / (1.f - sv);
  }
}

// ---------------- K5: fused GEMM + exp(d) partial sums ----------------
// exp(arccosh(x)) = x + sqrt(x^2-1): no exp/log in the hot loop.
__global__ __launch_bounds__(256) void k5_gemm() {
  __shared__ float As[KC][BBM + 2];   // stride 130: conflict-free transpose stores
  __shared__ float Bs[KC][BBN + 2];
  __shared__ float red[BBM][17];

  int nt = blockIdx.x;          // 0..390
  int bt = blockIdx.y;          // 0..7
  int b0 = bt * BBM, n0 = nt * BBN;
  int t = threadIdx.x;
  int tx = t & 15, ty = t >> 4;

  int lrow0 = t >> 2;           // 0..63
  int lk = (t & 3) << 2;        // 0,4,8,12

  float4 a_reg[2], b_reg[2];
#pragma unroll
  for (int q = 0; q < 2; q++) {
    int row = lrow0 + q * 64;
    a_reg[q] = *(const float4*)&g_Pi[(b0 + row) * NTOP + lk];
    int n = n0 + row;
    b_reg[q] = (n < NP) ? *(const float4*)&g_X[n * NTOP + lk]
                        : make_float4(0.f, 0.f, 0.f, 0.f);
  }

  float acc[8][8];
#pragma unroll
  for (int i = 0; i < 8; i++)
#pragma unroll
    for (int j = 0; j < 8; j++) acc[i][j] = 0.f;

  for (int c = 0; c < NTOP / KC; c++) {
    __syncthreads();
#pragma unroll
    for (int q = 0; q < 2; q++) {
      int row = lrow0 + q * 64;
      As[lk + 0][row] = a_reg[q].x;  As[lk + 1][row] = a_reg[q].y;
      As[lk + 2][row] = a_reg[q].z;  As[lk + 3][row] = a_reg[q].w;
      Bs[lk + 0][row] = b_reg[q].x;  Bs[lk + 1][row] = b_reg[q].y;
      Bs[lk + 2][row] = b_reg[q].z;  Bs[lk + 3][row] = b_reg[q].w;
    }
    __syncthreads();
    if (c + 1 < NTOP / KC) {
      int k0 = (c + 1) * KC;
#pragma unroll
      for (int q = 0; q < 2; q++) {
        int row = lrow0 + q * 64;
        a_reg[q] = *(const float4*)&g_Pi[(b0 + row) * NTOP + k0 + lk];
        int n = n0 + row;
        b_reg[q] = (n < NP) ? *(const float4*)&g_X[n * NTOP + k0 + lk]
                            : make_float4(0.f, 0.f, 0.f, 0.f);
      }
    }
#pragma unroll
    for (int k = 0; k < KC; k++) {
      float av[8], bv[8];
#pragma unroll
      for (int i = 0; i < 8; i++) av[i] = As[k][ty + 16 * i];
#pragma unroll
      for (int j = 0; j < 8; j++) bv[j] = Bs[k][tx + 16 * j];
#pragma unroll
      for (int i = 0; i < 8; i++)
#pragma unroll
        for (int j = 0; j < 8; j++) acc[i][j] = fmaf(av[i], bv[j], acc[i][j]);
    }
  }

  // epilogue: e = x + sqrt(x^2 - 1), masked past N
  float svn[8], rvn[8];
  bool valid[8];
#pragma unroll
  for (int j = 0; j < 8; j++) {
    int n = n0 + tx + 16 * j;
    valid[j] = (n < NP);
    svn[j] = valid[j] ? g_sv[n] : 0.f;
    rvn[j] = valid[j] ? g_rv[n] : 0.f;
  }
  float rowsum[8];
#pragma unroll
  for (int i = 0; i < 8; i++) {
    int rb = b0 + ty + 16 * i;
    float sub = g_su[rb], rub = g_ru[rb];
    float rs = 0.f;
#pragma unroll
    for (int j = 0; j < 8; j++) {
      if (valid[j]) {
        float sq = fmaxf(sub + svn[j] - 2.f * acc[i][j], 0.f);
        float xx = fmaf(2.f * sq, rub * rvn[j], 1.f);
        xx = fmaxf(xx, 1.0f + 1e-7f);
        rs += xx + sqrtf(fmaf(xx, xx, -1.f));
      }
    }
    rowsum[i] = rs;
  }
#pragma unroll
  for (int i = 0; i < 8; i++) red[ty + 16 * i][tx] = rowsum[i];
  __syncthreads();
  if (t < BBM) {
    float s = 0.f;
#pragma unroll
    for (int q = 0; q < 16; q++) s += red[t][q];
    g_partial[(b0 + t) * NTILES + nt] = s;   // unique slot: deterministic
  }
}

// ---------------- K7: d[b, j[b]] ----------------
__global__ void k7_dj(const int* __restrict__ jidx) {
  int b = blockIdx.x;
  int lane = threadIdx.x;
  int jb = jidx[b];
  float dot = 0.f;
  for (int k = lane; k < NTOP; k += 32) dot += g_Pi[b * NTOP + k] * g_X[jb * NTOP + k];
#pragma unroll
  for (int o = 16; o > 0; o >>= 1) dot += __shfl_down_sync(0xffffffffu, dot, o);
  if (lane == 0) {
    float sq = fmaxf(g_su[b] + g_sv[jb] - 2.f * dot, 0.f);
    float xx = fmaf(2.f * sq, g_ru[b] * g_rv[jb], 1.f);
    xx = fmaxf(xx, 1.0f + 1e-7f);
    g_dj[b] = logf(xx + sqrtf(fmaf(xx, xx, -1.f)));
  }
}

// ---------------- K6: per-row logsumexp finish + kld term ----------------
__global__ __launch_bounds__(256) void k6_lse(const float* __restrict__ pij) {
  int b = blockIdx.x, t = threadIdx.x;
  float s = 0.f;
  for (int q = t; q < NTILES; q += 256) s += g_partial[b * NTILES + q];
  __shared__ float sh[256];
  sh[t] = s; __syncthreads();
  for (int w = 128; w > 0; w >>= 1) { if (t < w) sh[t] += sh[t + w]; __syncthreads(); }
  if (t == 0) {
    float L = logf(sh[0]);
    float pb = pij[b];
    g_kldb[b] = pb * (logf(pb) - (g_dj[b] - L));
  }
}

// ---------------- K8: final scalar combine ----------------
__global__ __launch_bounds__(256) void k8_final(float* __restrict__ out) {
  int t = threadIdx.x;
  __shared__ double shd[256];
  double s1 = 0.0;
  for (int b = t; b < BATCH; b += 256) s1 += (double)g_kldb[b];
  double s2 = 0.0;
  for (int q = t; q < K1_BLOCKS; q += 256) s2 += (double)g_rp[q];
  shd[t] = s1; __syncthreads();
  for (int w = 128; w > 0; w >>= 1) { if (t < w) shd[t] += shd[t + w]; __syncthreads(); }
  double kldsum = shd[0];
  __syncthreads();
  shd[t] = s2; __syncthreads();
  for (int w = 128; w > 0; w >>= 1) { if (t < w) shd[t] += shd[t + w]; __syncthreads(); }
  if (t == 0) {
    double frac = 1024.0 / (50000.0 * 50000.0);
    out[0] = (float)(kldsum + (-0.5 * shd[0]) * frac);
  }
}

// ---------------- host launcher ----------------
extern "C" void kernel_launch(void* const* d_in, const int* in_sizes, int n_in,
                              void* d_out, int out_size) {
  const float* pij = (const float*)d_in[0];
  const float* mu  = (const float*)d_in[1];
  const float* lv  = (const float*)d_in[2];
  const int*   ii  = (const int*)d_in[3];
  const int*   jj  = (const int*)d_in[4];
  float* out = (float*)d_out;

  // key(42) = (0,42); split -> kx = (w0(0,2), w0(1,3)), ki = (w1(0,2), w1(1,3))
  unsigned int A0, B0, A1, B1;
  tf2x32(0u, 42u, 0u, 2u, A0, B0);
  tf2x32(0u, 42u, 1u, 3u, A1, B1);

  k1_sample_x<<<K1_BLOCKS, 256>>>(mu, lv, A0, A1);
  k3_sample_xi<<<K3_BLOCKS, 256>>>(mu, lv, ii, B0, B1);
  k_transform<<<NP, 256>>>(0);
  k_transform<<<BATCH, 256>>>(1);
  k5_gemm<<<dim3(NTILES, BATCH / BBM), 256>>>();
  k7_dj<<<BATCH, 32>>>(jj);
  k6_lse<<<BATCH, 256>>>(pij);
  k8_final<<<1, 256>>>(out);
}

// round 5
// speedup vs baseline: 1.9093x; 1.9093x over previous
#include <cuda_runtime.h>
#include <cuda_bf16.h>
#include <cstdint>

#define NP 50000
#define NPPAD 50048
#define NTOP 256
#define BATCH 1024
#define HALF_X 6400000
#define HALF_I 131072
#define KLB 25000
#define NTILES 391
#define NG 18

// dynamic smem layout (byte offsets)
#define SMO_A   0         // 4 chunks x {Ah,Al} x 16KB = 128KB
#define SMO_B   131072    // 2 stages x {Bh,Bl} x 16KB = 64KB
#define SMO_SV  196608    // 2 x 128 float2 = 2KB
#define SMO_RED 198656    // 128 x 2 float = 1KB
#define SMT_TOT 199680

__device__ __align__(256) __nv_bfloat16 g_Bh[NPPAD * NTOP];
__device__ __align__(256) __nv_bfloat16 g_Bl[NPPAD * NTOP];
__device__ __align__(256) __nv_bfloat16 g_Ah[BATCH * NTOP];
__device__ __align__(256) __nv_bfloat16 g_Al[BATCH * NTOP];
__device__ float2 g_svrv[NPPAD];
__device__ float g_su[BATCH], g_ru[BATCH];
__device__ float g_partial[BATCH * NTILES];
__device__ float g_dj[BATCH], g_kldb[BATCH], g_rp[KLB];

// ---------- PTX helpers (all plain sm_100-legal: sm_80-era features) ----------
__device__ __forceinline__ uint32_t smem_u32(const void* p) {
  uint32_t a;
  asm("{ .reg .u64 t; cvta.to.shared.u64 t, %1; cvt.u32.u64 %0, t; }" : "=r"(a) : "l"(p));
  return a;
}
#define SWZ128(o) ((o) ^ (((o) >> 3) & 0x70))
__device__ __forceinline__ void cpa16(uint32_t d, const void* s) {
  asm volatile("cp.async.cg.shared.global [%0], [%1], 16;" :: "r"(d), "l"(s));
}
__device__ __forceinline__ void cpa8(uint32_t d, const void* s) {
  asm volatile("cp.async.ca.shared.global [%0], [%1], 8;" :: "r"(d), "l"(s));
}
#define CPCOMMIT() asm volatile("cp.async.commit_group;" ::: "memory")
#define CPWAIT(n)  asm volatile("cp.async.wait_group %0;" :: "n"(n) : "memory")

#define LDSM4(r, addr) \
  asm volatile("ldmatrix.sync.aligned.m8n8.x4.shared.b16 {%0,%1,%2,%3}, [%4];" \
    : "=r"((r)[0]), "=r"((r)[1]), "=r"((r)[2]), "=r"((r)[3]) : "r"(addr))

#define MMA16816(d, a, b0r, b1r) \
  asm volatile("mma.sync.aligned.m16n8k16.row.col.f32.bf16.bf16.f32 " \
    "{%0,%1,%2,%3}, {%4,%5,%6,%7}, {%8,%9}, {%0,%1,%2,%3};" \
    : "+f"((d)[0]), "+f"((d)[1]), "+f"((d)[2]), "+f"((d)[3]) \
    : "r"((a)[0]), "r"((a)[1]), "r"((a)[2]), "r"((a)[3]), "r"(b0r), "r"(b1r))

// ---------- Threefry-2x32 (exact JAX) ----------
__host__ __device__ __forceinline__ void tf2x32(unsigned k0, unsigned k1,
                                                unsigned c0, unsigned c1,
                                                unsigned& o0, unsigned& o1) {
  unsigned ks2 = k0 ^ k1 ^ 0x1BD11BDAu;
  unsigned x0 = c0 + k0, x1 = c1 + k1;
#define TF_R(d) { x0 += x1; x1 = (x1 << (d)) | (x1 >> (32 - (d))); x1 ^= x0; }
  TF_R(13) TF_R(15) TF_R(26) TF_R(6)   x0 += k1;  x1 += ks2 + 1u;
  TF_R(17) TF_R(29) TF_R(16) TF_R(24)  x0 += ks2; x1 += k0 + 2u;
  TF_R(13) TF_R(15) TF_R(26) TF_R(6)   x0 += k0;  x1 += k1 + 3u;
  TF_R(17) TF_R(29) TF_R(16) TF_R(24)  x0 += k1;  x1 += ks2 + 4u;
  TF_R(13) TF_R(15) TF_R(26) TF_R(6)   x0 += ks2; x1 += k0 + 5u;
#undef TF_R
  o0 = x0; o1 = x1;
}
__device__ __forceinline__ float bits_to_normal(unsigned bits) {
  float f = __uint_as_float((bits >> 9) | 0x3f800000u) - 1.0f;
  float lo = __uint_as_float(0xBF7FFFFFu);
  return 1.41421356237f * erfinvf(fmaxf(lo, fmaf(f, 2.0f, lo)));
}
__device__ __forceinline__ float blockReduce256(float v, volatile float* sh) {
#pragma unroll
  for (int o = 16; o > 0; o >>= 1) v += __shfl_down_sync(0xffffffffu, v, o);
  int lane = threadIdx.x & 31, w = threadIdx.x >> 5;
  if (lane == 0) sh[w] = v;
  __syncthreads();
  if (w == 0) {
    float r = (lane < 8) ? sh[lane] : 0.f;
#pragma unroll
    for (int o = 4; o > 0; o >>= 1) r += __shfl_down_sync(0xffffffffu, r, o);
    if (lane == 0) sh[8] = r;
  }
  __syncthreads();
  float out = sh[8];
  __syncthreads();
  return out;
}

// ---------- K0: zero the B padding rows ----------
__global__ __launch_bounds__(256) void k0_pad() {
  int i = blockIdx.x * 256 + threadIdx.x;
  if (i < (NPPAD - NP) * NTOP) {
    g_Bh[NP * NTOP + i] = __float2bfloat16(0.f);
    g_Bl[NP * NTOP + i] = __float2bfloat16(0.f);
    if (i < NPPAD - NP) g_svrv[NP + i] = make_float2(0.f, 1.f);
  }
}

// ---------- fused sample + double Poincare transform ----------
__device__ __forceinline__ float do_row(float m, float l, unsigned bits, int row,
                                        __nv_bfloat16* Bh, __nv_bfloat16* Bl,
                                        float2* svrv, float* su, float* ru,
                                        volatile float* sh, int is_batch) {
  int t = threadIdx.x;
  float x = fmaf(bits_to_normal(bits), expf(0.5f * l), m);
  float kl = 1.0f + l - m * m - expf(l);
  float sx = blockReduce256(x * x, sh);
  float y = x / (1.f + sqrtf(1.f + sx));
  float sy = blockReduce256(y * y, sh);
  float p = y / (1.f + sqrtf(1.f + sy));
  __nv_bfloat16 hi = __float2bfloat16_rn(p);
  Bh[row * NTOP + t] = hi;
  Bl[row * NTOP + t] = __float2bfloat16_rn(p - __bfloat162float(hi));
  float sp = blockReduce256(p * p, sh);
  if (t == 0) {
    float sv = fminf(fmaxf(sp, 0.f), 1.f - 1e-5f);
    float rv = 1.f / (1.f - sv);
    if (is_batch) { su[row] = sv; ru[row] = rv; }
    else svrv[row] = make_float2(sv, rv);
  }
  return kl;
}

__global__ __launch_bounds__(256) void kA(const float* __restrict__ mu,
                                          const float* __restrict__ lv,
                                          unsigned kx0, unsigned kx1) {
  __shared__ float sh[16];
  int r = blockIdx.x, t = threadIdx.x;
  int f0 = r * NTOP + t;
  unsigned b0, b1;
  tf2x32(kx0, kx1, (unsigned)f0, (unsigned)(f0 + HALF_X), b0, b1);
  int r2 = r + 25000;
  float kl = do_row(mu[f0], lv[f0], b0, r, g_Bh, g_Bl, g_svrv, 0, 0, sh, 0);
  kl += do_row(mu[r2 * NTOP + t], lv[r2 * NTOP + t], b1, r2, g_Bh, g_Bl, g_svrv, 0, 0, sh, 0);
  float s = blockReduce256(kl, sh);
  if (t == 0) g_rp[r] = s;
}

__global__ __launch_bounds__(256) void kB(const float* __restrict__ mu,
                                          const float* __restrict__ lv,
                                          const int* __restrict__ iidx,
                                          unsigned ki0, unsigned ki1) {
  __shared__ float sh[16];
  int r = blockIdx.x, t = threadIdx.x;
  int f0 = r * NTOP + t;
  unsigned b0, b1;
  tf2x32(ki0, ki1, (unsigned)f0, (unsigned)(f0 + HALF_I), b0, b1);
  int r2 = r + 512;
  int a0 = iidx[r] * NTOP + t, a1 = iidx[r2] * NTOP + t;
  do_row(mu[a0], lv[a0], b0, r, g_Ah, g_Al, 0, g_su, g_ru, sh, 1);
  do_row(mu[a1], lv[a1], b1, r2, g_Ah, g_Al, 0, g_su, g_ru, sh, 1);
}

// ---------- K5: persistent mma.sync bf16x3 GEMM + fused exp(d) epilogue ----------
__device__ __forceinline__ void load_chunk(uint32_t sdst, const __nv_bfloat16* g,
                                           int row0, int c, int t) {
#pragma unroll
  for (int q = 0; q < 4; q++) {
    int idx = q * 256 + t, r = idx >> 3, i = idx & 7;
    cpa16(sdst + SWZ128(r * 128 + i * 16),
          (const char*)g + (size_t)(row0 + r) * 512 + c * 128 + i * 16);
  }
}

__global__ __launch_bounds__(256, 1) void k5_gemm() {
  extern __shared__ char smc[];
  uint32_t sb = smem_u32(smc);
  int t = threadIdx.x, w = t >> 5, lane = t & 31;
  int wm = w & 3, wn = w >> 2;
  int grp = blockIdx.x, b0 = blockIdx.y * 128;
  int ntiles = (NTILES - grp + NG - 1) / NG;   // tiles grp, grp+NG, ...

  // su/ru for this thread's 4 accumulator rows
  float sub[4], rub2[4];
#pragma unroll
  for (int i = 0; i < 4; i++) {
    int row = b0 + wm * 32 + (i >> 1) * 16 + (lane >> 2) + (i & 1) * 8;
    sub[i] = g_su[row];
    rub2[i] = 2.f * g_ru[row];
  }

  // startup: resident A (4 chunks x hi/lo), B chunk0 of first tile, svrv
#pragma unroll
  for (int c = 0; c < 4; c++) {
    load_chunk(sb + SMO_A + c * 32768,         g_Ah, b0, c, t);
    load_chunk(sb + SMO_A + c * 32768 + 16384, g_Al, b0, c, t);
  }
  load_chunk(sb + SMO_B,         g_Bh, grp * 128, 0, t);
  load_chunk(sb + SMO_B + 16384, g_Bl, grp * 128, 0, t);
  if (t < 128) cpa8(sb + SMO_SV + t * 8, &g_svrv[grp * 128 + t]);
  CPCOMMIT();

  unsigned cc = 0;
  for (int ti = 0; ti < ntiles; ti++) {
    int nt = grp + ti * NG;
    float acc[2][8][4];
#pragma unroll
    for (int a = 0; a < 2; a++)
#pragma unroll
      for (int b = 0; b < 8; b++)
#pragma unroll
        for (int e = 0; e < 4; e++) acc[a][b][e] = 0.f;

    for (int c = 0; c < 4; c++, cc++) {
      bool has_next = (c < 3) || (ti < ntiles - 1);
      if (has_next) {
        int nc = (c + 1) & 3;
        int nr = (c == 3) ? (nt + NG) * 128 : nt * 128;
        uint32_t bs = sb + SMO_B + ((cc + 1) & 1) * 32768;
        load_chunk(bs,         g_Bh, nr, nc, t);
        load_chunk(bs + 16384, g_Bl, nr, nc, t);
        if (c == 3 && t < 128)
          cpa8(sb + SMO_SV + ((ti + 1) & 1) * 1024 + t * 8, &g_svrv[nr + t]);
        CPCOMMIT();
        CPWAIT(1);
      } else {
        CPWAIT(0);
      }
      __syncthreads();       // stage data visible to all warps

      uint32_t ab = sb + SMO_A + c * 32768;
      uint32_t bb = sb + SMO_B + (cc & 1) * 32768;
#pragma unroll
      for (int ks = 0; ks < 4; ks++) {
        uint32_t aH[2][4], aL[2][4];
#pragma unroll
        for (int mt = 0; mt < 2; mt++) {
          int r = wm * 32 + mt * 16 + (lane & 15);
          int kg = ks * 2 + (lane >> 4);
          uint32_t ad = ab + r * 128 + ((kg ^ (r & 7)) * 16);
          LDSM4(aH[mt], ad);
          LDSM4(aL[mt], ad + 16384);
        }
#pragma unroll
        for (int q = 0; q < 4; q++) {
          uint32_t bH[4], bL[4];
          {
            int r = wn * 64 + q * 16 + (lane & 15);
            int kg = ks * 2 + (lane >> 4);
            uint32_t bd = bb + r * 128 + ((kg ^ (r & 7)) * 16);
            LDSM4(bH, bd);
            LDSM4(bL, bd + 16384);
          }
#pragma unroll
          for (int mt = 0; mt < 2; mt++) {
            MMA16816(acc[mt][2 * q],     aH[mt], bH[0], bH[2]);
            MMA16816(acc[mt][2 * q],     aH[mt], bL[0], bL[2]);
            MMA16816(acc[mt][2 * q],     aL[mt], bH[0], bH[2]);
            MMA16816(acc[mt][2 * q + 1], aH[mt], bH[1], bH[3]);
            MMA16816(acc[mt][2 * q + 1], aH[mt], bL[1], bL[3]);
            MMA16816(acc[mt][2 * q + 1], aL[mt], bH[1], bH[3]);
          }
        }
      }
      __syncthreads();       // all reads done before next prefetch overwrites
    }

    // epilogue: e = x + sqrt(x^2-1) from register accumulators
    const float2* svp = (const float2*)(smc + SMO_SV + (ti & 1) * 1024);
    int nbase = nt * 128;
    float rs[4] = {0.f, 0.f, 0.f, 0.f};
#pragma unroll
    for (int mt = 0; mt < 2; mt++)
#pragma unroll
      for (int q = 0; q < 8; q++)
#pragma unroll
        for (int e = 0; e < 4; e++) {
          int nl = wn * 64 + q * 8 + 2 * (lane & 3) + (e & 1);
          if (nbase + nl < NP) {
            float2 sr = svp[nl];
            int ri = mt * 2 + (e >> 1);
            float qd = fmaxf(fmaf(acc[mt][q][e], -2.f, sub[ri] + sr.x), 0.f);
            float xx = fmaxf(fmaf(qd, rub2[ri] * sr.y, 1.f), 1.0f + 1e-7f);
            float s;
            asm("sqrt.approx.f32 %0, %1;" : "=f"(s) : "f"(fmaf(xx, xx, -1.f)));
            rs[ri] += xx + s;
          }
        }
    float* red = (float*)(smc + SMO_RED);
#pragma unroll
    for (int i = 0; i < 4; i++) {
      rs[i] += __shfl_xor_sync(0xffffffffu, rs[i], 1);
      rs[i] += __shfl_xor_sync(0xffffffffu, rs[i], 2);
      if ((lane & 3) == 0) {
        int row = wm * 32 + (i >> 1) * 16 + (lane >> 2) + (i & 1) * 8;
        red[row * 2 + wn] = rs[i];
      }
    }
    __syncthreads();
    if (t < 128)
      g_partial[(b0 + t) * NTILES + nt] = red[t * 2] + red[t * 2 + 1];
    __syncthreads();
  }
}

// ---------- tails ----------
__global__ void k7_dj(const int* __restrict__ jidx) {
  int b = blockIdx.x, lane = threadIdx.x;
  int jb = jidx[b];
  float dot = 0.f;
  for (int k = lane; k < NTOP; k += 32) {
    float a = __bfloat162float(g_Ah[b * NTOP + k]) + __bfloat162float(g_Al[b * NTOP + k]);
    float v = __bfloat162float(g_Bh[jb * NTOP + k]) + __bfloat162float(g_Bl[jb * NTOP + k]);
    dot += a * v;
  }
#pragma unroll
  for (int o = 16; o > 0; o >>= 1) dot += __shfl_down_sync(0xffffffffu, dot, o);
  if (lane == 0) {
    float2 sr = g_svrv[jb];
    float sq = fmaxf(g_su[b] + sr.x - 2.f * dot, 0.f);
    float xx = fmaxf(fmaf(2.f * sq, g_ru[b] * sr.y, 1.f), 1.0f + 1e-7f);
    g_dj[b] = logf(xx + sqrtf(fmaf(xx, xx, -1.f)));
  }
}

__global__ __launch_bounds__(256) void k6_lse(const float* __restrict__ pij) {
  int b = blockIdx.x, t = threadIdx.x;
  float s = 0.f;
  for (int q = t; q < NTILES; q += 256) s += g_partial[b * NTILES + q];
  __shared__ float sh[256];
  sh[t] = s; __syncthreads();
  for (int w = 128; w > 0; w >>= 1) { if (t < w) sh[t] += sh[t + w]; __syncthreads(); }
  if (t == 0) {
    float pb = pij[b];
    g_kldb[b] = pb * (logf(pb) - (g_dj[b] - logf(sh[0])));
  }
}

__global__ __launch_bounds__(256) void k8_final(float* __restrict__ out) {
  int t = threadIdx.x;
  __shared__ double shd[256];
  double s1 = 0.0, s2 = 0.0;
  for (int b = t; b < BATCH; b += 256) s1 += (double)g_kldb[b];
  for (int q = t; q < KLB; q += 256) s2 += (double)g_rp[q];
  shd[t] = s1; __syncthreads();
  for (int w = 128; w > 0; w >>= 1) { if (t < w) shd[t] += shd[t + w]; __syncthreads(); }
  double kldsum = shd[0]; __syncthreads();
  shd[t] = s2; __syncthreads();
  for (int w = 128; w > 0; w >>= 1) { if (t < w) shd[t] += shd[t + w]; __syncthreads(); }
  if (t == 0)
    out[0] = (float)(kldsum + (-0.5 * shd[0]) * (1024.0 / (50000.0 * 50000.0)));
}

extern "C" void kernel_launch(void* const* d_in, const int* in_sizes, int n_in,
                              void* d_out, int out_size) {
  const float* pij = (const float*)d_in[0];
  const float* mu  = (const float*)d_in[1];
  const float* lv  = (const float*)d_in[2];
  const int*   ii  = (const int*)d_in[3];
  const int*   jj  = (const int*)d_in[4];
  float* out = (float*)d_out;

  unsigned A0, B0, A1, B1;
  tf2x32(0u, 42u, 0u, 2u, A0, B0);   // kx
  tf2x32(0u, 42u, 1u, 3u, A1, B1);   // ki

  cudaFuncSetAttribute(k5_gemm, cudaFuncAttributeMaxDynamicSharedMemorySize, SMT_TOT);

  k0_pad<<<48, 256>>>();
  kA<<<25000, 256>>>(mu, lv, A0, A1);
  kB<<<512, 256>>>(mu, lv, ii, B0, B1);
  k5_gemm<<<dim3(NG, 8), 256, SMT_TOT>>>();
  k7_dj<<<BATCH, 32>>>(jj);
  k6_lse<<<BATCH, 256>>>(pij);
  k8_final<<<1, 256>>>(out);
}

// round 6
// speedup vs baseline: 2.0913x; 1.0954x over previous
#include <cuda_runtime.h>
#include <cuda_bf16.h>
#include <cstdint>

#define NP 50000
#define NPPAD 50048
#define NTOP 256
#define BATCH 1024
#define HALF_X 6400000
#define HALF_I 131072
#define KLB 25000
#define NTILES 391
#define NG 18

// dynamic smem layout (byte offsets)
#define SMO_A   0         // 4 chunks x {Ah,Al} x 16KB = 128KB
#define SMO_B   131072    // 2 stages x {Bh,Bl} x 16KB = 64KB
#define SMO_SV  196608    // 2 x 128 float2 = 2KB
#define SMO_RED 198656    // 128 x 2 float = 1KB
#define SMT_TOT 199680

__device__ __align__(256) __nv_bfloat16 g_Bh[NPPAD * NTOP];
__device__ __align__(256) __nv_bfloat16 g_Bl[NPPAD * NTOP];
__device__ __align__(256) __nv_bfloat16 g_Ah[BATCH * NTOP];
__device__ __align__(256) __nv_bfloat16 g_Al[BATCH * NTOP];
__device__ float2 g_svrv[NPPAD];
__device__ float g_su[BATCH], g_ru[BATCH];
__device__ float g_partial[BATCH * NTILES];
__device__ float g_dj[BATCH], g_kldb[BATCH], g_rp[KLB];

// ---------- PTX helpers (plain sm_100-legal) ----------
__device__ __forceinline__ uint32_t smem_u32(const void* p) {
  uint32_t a;
  asm("{ .reg .u64 t; cvta.to.shared.u64 t, %1; cvt.u32.u64 %0, t; }" : "=r"(a) : "l"(p));
  return a;
}
#define SWZ128(o) ((o) ^ (((o) >> 3) & 0x70))
__device__ __forceinline__ void cpa16(uint32_t d, const void* s) {
  asm volatile("cp.async.cg.shared.global [%0], [%1], 16;" :: "r"(d), "l"(s));
}
__device__ __forceinline__ void cpa8(uint32_t d, const void* s) {
  asm volatile("cp.async.ca.shared.global [%0], [%1], 8;" :: "r"(d), "l"(s));
}
#define CPCOMMIT() asm volatile("cp.async.commit_group;" ::: "memory")
#define CPWAIT0()  asm volatile("cp.async.wait_group 0;" ::: "memory")

#define LDSM4(r, addr) \
  asm volatile("ldmatrix.sync.aligned.m8n8.x4.shared.b16 {%0,%1,%2,%3}, [%4];" \
    : "=r"((r)[0]), "=r"((r)[1]), "=r"((r)[2]), "=r"((r)[3]) : "r"(addr))

#define MMA16816(d, a, b0r, b1r) \
  asm volatile("mma.sync.aligned.m16n8k16.row.col.f32.bf16.bf16.f32 " \
    "{%0,%1,%2,%3}, {%4,%5,%6,%7}, {%8,%9}, {%0,%1,%2,%3};" \
    : "+f"((d)[0]), "+f"((d)[1]), "+f"((d)[2]), "+f"((d)[3]) \
    : "r"((a)[0]), "r"((a)[1]), "r"((a)[2]), "r"((a)[3]), "r"(b0r), "r"(b1r))

// ---------- Threefry-2x32 (exact JAX) ----------
__host__ __device__ __forceinline__ void tf2x32(unsigned k0, unsigned k1,
                                                unsigned c0, unsigned c1,
                                                unsigned& o0, unsigned& o1) {
  unsigned ks2 = k0 ^ k1 ^ 0x1BD11BDAu;
  unsigned x0 = c0 + k0, x1 = c1 + k1;
#define TF_R(d) { x0 += x1; x1 = (x1 << (d)) | (x1 >> (32 - (d))); x1 ^= x0; }
  TF_R(13) TF_R(15) TF_R(26) TF_R(6)   x0 += k1;  x1 += ks2 + 1u;
  TF_R(17) TF_R(29) TF_R(16) TF_R(24)  x0 += ks2; x1 += k0 + 2u;
  TF_R(13) TF_R(15) TF_R(26) TF_R(6)   x0 += k0;  x1 += k1 + 3u;
  TF_R(17) TF_R(29) TF_R(16) TF_R(24)  x0 += k1;  x1 += ks2 + 4u;
  TF_R(13) TF_R(15) TF_R(26) TF_R(6)   x0 += ks2; x1 += k0 + 5u;
#undef TF_R
  o0 = x0; o1 = x1;
}
__device__ __forceinline__ float bits_to_normal(unsigned bits) {
  float f = __uint_as_float((bits >> 9) | 0x3f800000u) - 1.0f;
  float lo = __uint_as_float(0xBF7FFFFFu);
  return 1.41421356237f * erfinvf(fmaxf(lo, fmaf(f, 2.0f, lo)));
}
__device__ __forceinline__ float wred(float v) {
#pragma unroll
  for (int o = 16; o > 0; o >>= 1) v += __shfl_xor_sync(0xffffffffu, v, o);
  return v;
}

// ---------- K0: zero the B padding rows ----------
__global__ __launch_bounds__(256) void k0_pad() {
  int i = blockIdx.x * 256 + threadIdx.x;
  if (i < (NPPAD - NP) * NTOP) {
    g_Bh[NP * NTOP + i] = __float2bfloat16(0.f);
    g_Bl[NP * NTOP + i] = __float2bfloat16(0.f);
    if (i < NPPAD - NP) g_svrv[NP + i] = make_float2(0.f, 1.f);
  }
}

// ---------- warp-per-row fused sample + double transform (no block barriers) ----------
// One x^2 reduce per row; sy = sx/s1^2 and sp = sy/s2^2 are analytic.
__device__ __forceinline__ void row_transform(const float* x, float sx, int row,
                                              __nv_bfloat16* Bh, __nv_bfloat16* Bl,
                                              float2* svrv, float* su, float* ru,
                                              int lane, int is_batch) {
  float s1 = 1.f + sqrtf(1.f + sx);
  float sy = sx / (s1 * s1);
  float s2 = 1.f + sqrtf(1.f + sy);
  float scale = 1.f / (s1 * s2);
#pragma unroll
  for (int k = 0; k < 8; k++) {
    float p = x[k] * scale;
    __nv_bfloat16 hi = __float2bfloat16_rn(p);
    int col = k * 32 + lane;
    Bh[row * NTOP + col] = hi;
    Bl[row * NTOP + col] = __float2bfloat16_rn(p - __bfloat162float(hi));
  }
  if (lane == 0) {
    float sp = sy / (s2 * s2);
    float sv = fminf(fmaxf(sp, 0.f), 1.f - 1e-5f);
    float rv = 1.f / (1.f - sv);
    if (is_batch) { su[row] = sv; ru[row] = rv; }
    else svrv[row] = make_float2(sv, rv);
  }
}

__global__ __launch_bounds__(256) void kA(const float* __restrict__ mu,
                                          const float* __restrict__ lv,
                                          unsigned kx0, unsigned kx1) {
  int w = threadIdx.x >> 5, lane = threadIdx.x & 31;
  int r = blockIdx.x * 8 + w;            // 3125 blocks -> r in [0,25000)
  int r2 = r + 25000;
  float x1[8], x2[8];
  float sx1 = 0.f, sx2 = 0.f, kl = 0.f;
#pragma unroll
  for (int k = 0; k < 8; k++) {
    int g = r * NTOP + k * 32 + lane;
    unsigned b0, b1;
    tf2x32(kx0, kx1, (unsigned)g, (unsigned)(g + HALF_X), b0, b1);
    float m1 = mu[g], l1 = lv[g];
    x1[k] = fmaf(bits_to_normal(b0), expf(0.5f * l1), m1);
    kl += 1.0f + l1 - m1 * m1 - expf(l1);
    int g2 = g + HALF_X;
    float m2 = mu[g2], l2 = lv[g2];
    x2[k] = fmaf(bits_to_normal(b1), expf(0.5f * l2), m2);
    kl += 1.0f + l2 - m2 * m2 - expf(l2);
    sx1 += x1[k] * x1[k];
    sx2 += x2[k] * x2[k];
  }
  sx1 = wred(sx1); sx2 = wred(sx2); kl = wred(kl);
  row_transform(x1, sx1, r,  g_Bh, g_Bl, g_svrv, 0, 0, lane, 0);
  row_transform(x2, sx2, r2, g_Bh, g_Bl, g_svrv, 0, 0, lane, 0);
  if (lane == 0) g_rp[r] = kl;
}

__global__ __launch_bounds__(256) void kB(const float* __restrict__ mu,
                                          const float* __restrict__ lv,
                                          const int* __restrict__ iidx,
                                          unsigned ki0, unsigned ki1) {
  int w = threadIdx.x >> 5, lane = threadIdx.x & 31;
  int r = blockIdx.x * 8 + w;            // 64 blocks -> r in [0,512)
  int r2 = r + 512;
  int i1 = iidx[r], i2 = iidx[r2];
  float x1[8], x2[8];
  float sx1 = 0.f, sx2 = 0.f;
#pragma unroll
  for (int k = 0; k < 8; k++) {
    int col = k * 32 + lane;
    int f = r * NTOP + col;
    unsigned b0, b1;
    tf2x32(ki0, ki1, (unsigned)f, (unsigned)(f + HALF_I), b0, b1);
    int a0 = i1 * NTOP + col, a1 = i2 * NTOP + col;
    x1[k] = fmaf(bits_to_normal(b0), expf(0.5f * lv[a0]), mu[a0]);
    x2[k] = fmaf(bits_to_normal(b1), expf(0.5f * lv[a1]), mu[a1]);
    sx1 += x1[k] * x1[k];
    sx2 += x2[k] * x2[k];
  }
  sx1 = wred(sx1); sx2 = wred(sx2);
  row_transform(x1, sx1, r,  g_Ah, g_Al, 0, g_su, g_ru, lane, 1);
  row_transform(x2, sx2, r2, g_Ah, g_Al, 0, g_su, g_ru, lane, 1);
}

// ---------- K5: persistent mma.sync bf16x3 GEMM + fused exp(d) epilogue ----------
__global__ __launch_bounds__(256, 1) void k5_gemm() {
  extern __shared__ char smc[];
  uint32_t sb = smem_u32(smc);
  int t = threadIdx.x, w = t >> 5, lane = t & 31;
  int wm = w & 3, wn = w >> 2;
  int grp = blockIdx.x, b0 = blockIdx.y * 128;
  int ntiles = (NTILES - grp + NG - 1) / NG;

  // per-thread cp.async offsets (precomputed once)
  int tr = t >> 3, li = t & 7;
  uint32_t dstoff[4];
#pragma unroll
  for (int q = 0; q < 4; q++)
    dstoff[q] = SWZ128((uint32_t)((q * 32 + tr) * 128 + li * 16));
  uint32_t soff = (uint32_t)(tr * 512 + li * 16);   // src byte offset within chunk rows
  const char* bhp = (const char*)g_Bh;
  const char* blp = (const char*)g_Bl;

  float sub[4], rub2[4];
#pragma unroll
  for (int i = 0; i < 4; i++) {
    int row = b0 + wm * 32 + (i >> 1) * 16 + (lane >> 2) + (i & 1) * 8;
    sub[i] = g_su[row];
    rub2[i] = 2.f * g_ru[row];
  }

  // startup: resident A (4 chunks x hi/lo), B chunk0 of first tile, svrv
#pragma unroll
  for (int c = 0; c < 4; c++) {
#pragma unroll
    for (int q = 0; q < 4; q++) {
      uint32_t so = (uint32_t)(b0 * 512 + c * 128 + q * 16384) + soff;
      cpa16(sb + SMO_A + c * 32768 +         dstoff[q], (const char*)g_Ah + so);
      cpa16(sb + SMO_A + c * 32768 + 16384 + dstoff[q], (const char*)g_Al + so);
    }
  }
  {
    uint32_t so = (uint32_t)(grp * 128 * 512) + soff;
#pragma unroll
    for (int q = 0; q < 4; q++) {
      cpa16(sb + SMO_B +         dstoff[q], bhp + so + q * 16384);
      cpa16(sb + SMO_B + 16384 + dstoff[q], blp + so + q * 16384);
    }
  }
  if (t < 128) cpa8(sb + SMO_SV + t * 8, &g_svrv[grp * 128 + t]);
  CPCOMMIT();

  // ldmatrix address components (hoisted)
  uint32_t a_base[2], a_xor[2];
#pragma unroll
  for (int mt = 0; mt < 2; mt++) {
    int r = wm * 32 + mt * 16 + (lane & 15);
    a_base[mt] = (uint32_t)(r * 128);
    a_xor[mt] = (uint32_t)(r & 7);
  }
  uint32_t b_base[4], b_xor[4];
#pragma unroll
  for (int q = 0; q < 4; q++) {
    int r = wn * 64 + q * 16 + (lane & 15);
    b_base[q] = (uint32_t)(r * 128);
    b_xor[q] = (uint32_t)(r & 7);
  }
  uint32_t ly = (uint32_t)(lane >> 4);

  unsigned cc = 0;
  for (int ti = 0; ti < ntiles; ti++) {
    int nt = grp + ti * NG;
    float acc[2][8][4];
#pragma unroll
    for (int a = 0; a < 2; a++)
#pragma unroll
      for (int b = 0; b < 8; b++)
#pragma unroll
        for (int e = 0; e < 4; e++) acc[a][b][e] = 0.f;

    for (int c = 0; c < 4; c++, cc++) {
      CPWAIT0();            // current stage's data (committed last iteration) done
      __syncthreads();      // visible everywhere; everyone done reading other stage
      bool has_next = (c < 3) || (ti < ntiles - 1);
      if (has_next) {
        int nc = (c + 1) & 3;
        int nrt = (c == 3) ? nt + NG : nt;
        uint32_t bs = sb + SMO_B + ((cc + 1) & 1) * 32768;
        uint32_t so = (uint32_t)(nrt * 128 * 512 + nc * 128) + soff;
#pragma unroll
        for (int q = 0; q < 4; q++) {
          cpa16(bs +         dstoff[q], bhp + so + q * 16384);
          cpa16(bs + 16384 + dstoff[q], blp + so + q * 16384);
        }
        if (c == 3 && t < 128)
          cpa8(sb + SMO_SV + ((ti + 1) & 1) * 1024 + t * 8, &g_svrv[nrt * 128 + t]);
        CPCOMMIT();
      }

      uint32_t ab = sb + SMO_A + c * 32768;
      uint32_t bb = sb + SMO_B + (cc & 1) * 32768;
#pragma unroll
      for (int ks = 0; ks < 4; ks++) {
        uint32_t kg = (uint32_t)(ks * 2) + ly;
        uint32_t aH[2][4], aL[2][4];
#pragma unroll
        for (int mt = 0; mt < 2; mt++) {
          uint32_t ad = ab + a_base[mt] + ((kg ^ a_xor[mt]) << 4);
          LDSM4(aH[mt], ad);
          LDSM4(aL[mt], ad + 16384);
        }
#pragma unroll
        for (int q = 0; q < 4; q++) {
          uint32_t bd = bb + b_base[q] + ((kg ^ b_xor[q]) << 4);
          uint32_t bH[4], bL[4];
          LDSM4(bH, bd);
          LDSM4(bL, bd + 16384);
#pragma unroll
          for (int mt = 0; mt < 2; mt++) {
            MMA16816(acc[mt][2 * q],     aH[mt], bH[0], bH[2]);
            MMA16816(acc[mt][2 * q + 1], aH[mt], bH[1], bH[3]);
          }
#pragma unroll
          for (int mt = 0; mt < 2; mt++) {
            MMA16816(acc[mt][2 * q],     aL[mt], bH[0], bH[2]);
            MMA16816(acc[mt][2 * q + 1], aL[mt], bH[1], bH[3]);
          }
#pragma unroll
          for (int mt = 0; mt < 2; mt++) {
            MMA16816(acc[mt][2 * q],     aH[mt], bL[0], bL[2]);
            MMA16816(acc[mt][2 * q + 1], aH[mt], bL[1], bL[3]);
          }
        }
      }
    }

    // epilogue: e = x + sqrt(x^2-1) from register accumulators
    const float2* svp = (const float2*)(smc + SMO_SV + (ti & 1) * 1024);
    int limit = NP - nt * 128;      // > 127 for all tiles except the last
    float rs[4] = {0.f, 0.f, 0.f, 0.f};
#pragma unroll
    for (int mt = 0; mt < 2; mt++)
#pragma unroll
      for (int q = 0; q < 8; q++)
#pragma unroll
        for (int e = 0; e < 4; e++) {
          int nl = wn * 64 + q * 8 + 2 * (lane & 3) + (e & 1);
          if (nl < limit) {
            float2 sr = svp[nl];
            int ri = mt * 2 + (e >> 1);
            float qd = fmaxf(fmaf(acc[mt][q][e], -2.f, sub[ri] + sr.x), 0.f);
            float xx = fmaxf(fmaf(qd, rub2[ri] * sr.y, 1.f), 1.0f + 1e-7f);
            float s;
            asm("sqrt.approx.f32 %0, %1;" : "=f"(s) : "f"(fmaf(xx, xx, -1.f)));
            rs[ri] += xx + s;
          }
        }
    float* red = (float*)(smc + SMO_RED);
#pragma unroll
    for (int i = 0; i < 4; i++) {
      rs[i] += __shfl_xor_sync(0xffffffffu, rs[i], 1);
      rs[i] += __shfl_xor_sync(0xffffffffu, rs[i], 2);
      if ((lane & 3) == 0) {
        int row = wm * 32 + (i >> 1) * 16 + (lane >> 2) + (i & 1) * 8;
        red[row * 2 + wn] = rs[i];
      }
    }
    __syncthreads();
    if (t < 128)
      g_partial[(b0 + t) * NTILES + nt] = red[t * 2] + red[t * 2 + 1];
    __syncthreads();
  }
}

// ---------- tails ----------
__global__ void k7_dj(const int* __restrict__ jidx) {
  int b = blockIdx.x, lane = threadIdx.x;
  int jb = jidx[b];
  float dot = 0.f;
  for (int k = lane; k < NTOP; k += 32) {
    float a = __bfloat162float(g_Ah[b * NTOP + k]) + __bfloat162float(g_Al[b * NTOP + k]);
    float v = __bfloat162float(g_Bh[jb * NTOP + k]) + __bfloat162float(g_Bl[jb * NTOP + k]);
    dot += a * v;
  }
#pragma unroll
  for (int o = 16; o > 0; o >>= 1) dot += __shfl_down_sync(0xffffffffu, dot, o);
  if (lane == 0) {
    float2 sr = g_svrv[jb];
    float sq = fmaxf(g_su[b] + sr.x - 2.f * dot, 0.f);
    float xx = fmaxf(fmaf(2.f * sq, g_ru[b] * sr.y, 1.f), 1.0f + 1e-7f);
    g_dj[b] = logf(xx + sqrtf(fmaf(xx, xx, -1.f)));
  }
}

__global__ __launch_bounds__(256) void k6_lse(const float* __restrict__ pij) {
  int b = blockIdx.x, t = threadIdx.x;
  float s = 0.f;
  for (int q = t; q < NTILES; q += 256) s += g_partial[b * NTILES + q];
  __shared__ float sh[256];
  sh[t] = s; __syncthreads();
  for (int w = 128; w > 0; w >>= 1) { if (t < w) sh[t] += sh[t + w]; __syncthreads(); }
  if (t == 0) {
    float pb = pij[b];
    g_kldb[b] = pb * (logf(pb) - (g_dj[b] - logf(sh[0])));
  }
}

__global__ __launch_bounds__(256) void k8_final(float* __restrict__ out) {
  int t = threadIdx.x;
  __shared__ double shd[256];
  double s1 = 0.0, s2 = 0.0;
  for (int b = t; b < BATCH; b += 256) s1 += (double)g_kldb[b];
  for (int q = t; q < KLB; q += 256) s2 += (double)g_rp[q];
  shd[t] = s1; __syncthreads();
  for (int w = 128; w > 0; w >>= 1) { if (t < w) shd[t] += shd[t + w]; __syncthreads(); }
  double kldsum = shd[0]; __syncthreads();
  shd[t] = s2; __syncthreads();
  for (int w = 128; w > 0; w >>= 1) { if (t < w) shd[t] += shd[t + w]; __syncthreads(); }
  if (t == 0)
    out[0] = (float)(kldsum + (-0.5 * shd[0]) * (1024.0 / (50000.0 * 50000.0)));
}

extern "C" void kernel_launch(void* const* d_in, const int* in_sizes, int n_in,
                              void* d_out, int out_size) {
  const float* pij = (const float*)d_in[0];
  const float* mu  = (const float*)d_in[1];
  const float* lv  = (const float*)d_in[2];
  const int*   ii  = (const int*)d_in[3];
  const int*   jj  = (const int*)d_in[4];
  float* out = (float*)d_out;

  unsigned A0, B0, A1, B1;
  tf2x32(0u, 42u, 0u, 2u, A0, B0);   // kx
  tf2x32(0u, 42u, 1u, 3u, A1, B1);   // ki

  cudaFuncSetAttribute(k5_gemm, cudaFuncAttributeMaxDynamicSharedMemorySize, SMT_TOT);

  k0_pad<<<48, 256>>>();
  kA<<<3125, 256>>>(mu, lv, A0, A1);
  kB<<<64, 256>>>(mu, lv, ii, B0, B1);
  k5_gemm<<<dim3(NG, 8), 256, SMT_TOT>>>();
  k7_dj<<<BATCH, 32>>>(jj);
  k6_lse<<<BATCH, 256>>>(pij);
  k8_final<<<1, 256>>>(out);
}

// round 7
// speedup vs baseline: 2.0986x; 1.0035x over previous
#include <cuda_runtime.h>
#include <cuda_bf16.h>
#include <cstdint>

#define NP 50000
#define NPPAD 50048
#define NTOP 256
#define BATCH 1024
#define HALF_X 6400000
#define HALF_I 131072
#define KLB 25000
#define NTILES 391
#define NG 18

// dynamic smem layout (byte offsets)
#define SMO_A   0         // 4 chunks x {Ah,Al} x 16KB = 128KB
#define SMO_B   131072    // 2 stages x {Bh,Bl} x 16KB = 64KB
#define SMO_SV  196608    // 2 x 128 float2 = 2KB
#define SMO_RED 198656    // 128 x 2 float = 1KB
#define SMT_TOT 199680

__device__ __align__(256) __nv_bfloat16 g_Bh[NPPAD * NTOP];
__device__ __align__(256) __nv_bfloat16 g_Bl[NPPAD * NTOP];
__device__ __align__(256) __nv_bfloat16 g_Ah[BATCH * NTOP];
__device__ __align__(256) __nv_bfloat16 g_Al[BATCH * NTOP];
__device__ float2 g_svrv[NPPAD];
__device__ float g_su[BATCH], g_ru[BATCH];
__device__ float g_partial[BATCH * NTILES];
__device__ float g_dj[BATCH], g_kldb[BATCH], g_rp[KLB];

// ---------- PTX helpers (plain sm_100-legal) ----------
__device__ __forceinline__ uint32_t smem_u32(const void* p) {
  uint32_t a;
  asm("{ .reg .u64 t; cvta.to.shared.u64 t, %1; cvt.u32.u64 %0, t; }" : "=r"(a) : "l"(p));
  return a;
}
#define SWZ128(o) ((o) ^ (((o) >> 3) & 0x70))
__device__ __forceinline__ void cpa16(uint32_t d, const void* s) {
  asm volatile("cp.async.cg.shared.global [%0], [%1], 16;" :: "r"(d), "l"(s));
}
__device__ __forceinline__ void cpa8(uint32_t d, const void* s) {
  asm volatile("cp.async.ca.shared.global [%0], [%1], 8;" :: "r"(d), "l"(s));
}
#define CPCOMMIT() asm volatile("cp.async.commit_group;" ::: "memory")
#define CPWAIT0()  asm volatile("cp.async.wait_group 0;" ::: "memory")

#define LDSM4(r, addr) \
  asm volatile("ldmatrix.sync.aligned.m8n8.x4.shared.b16 {%0,%1,%2,%3}, [%4];" \
    : "=r"((r)[0]), "=r"((r)[1]), "=r"((r)[2]), "=r"((r)[3]) : "r"(addr))

#define MMA16816(d, a, b0r, b1r) \
  asm volatile("mma.sync.aligned.m16n8k16.row.col.f32.bf16.bf16.f32 " \
    "{%0,%1,%2,%3}, {%4,%5,%6,%7}, {%8,%9}, {%0,%1,%2,%3};" \
    : "+f"((d)[0]), "+f"((d)[1]), "+f"((d)[2]), "+f"((d)[3]) \
    : "r"((a)[0]), "r"((a)[1]), "r"((a)[2]), "r"((a)[3]), "r"(b0r), "r"(b1r))

// ---------- Threefry-2x32 (exact JAX) ----------
__host__ __device__ __forceinline__ void tf2x32(unsigned k0, unsigned k1,
                                                unsigned c0, unsigned c1,
                                                unsigned& o0, unsigned& o1) {
  unsigned ks2 = k0 ^ k1 ^ 0x1BD11BDAu;
  unsigned x0 = c0 + k0, x1 = c1 + k1;
#define TF_R(d) { x0 += x1; x1 = (x1 << (d)) | (x1 >> (32 - (d))); x1 ^= x0; }
  TF_R(13) TF_R(15) TF_R(26) TF_R(6)   x0 += k1;  x1 += ks2 + 1u;
  TF_R(17) TF_R(29) TF_R(16) TF_R(24)  x0 += ks2; x1 += k0 + 2u;
  TF_R(13) TF_R(15) TF_R(26) TF_R(6)   x0 += k0;  x1 += k1 + 3u;
  TF_R(17) TF_R(29) TF_R(16) TF_R(24)  x0 += k1;  x1 += ks2 + 4u;
  TF_R(13) TF_R(15) TF_R(26) TF_R(6)   x0 += ks2; x1 += k0 + 5u;
#undef TF_R
  o0 = x0; o1 = x1;
}
__device__ __forceinline__ float bits_to_normal(unsigned bits) {
  float f = __uint_as_float((bits >> 9) | 0x3f800000u) - 1.0f;
  float lo = __uint_as_float(0xBF7FFFFFu);
  return 1.41421356237f * erfinvf(fmaxf(lo, fmaf(f, 2.0f, lo)));
}
__device__ __forceinline__ float wred(float v) {
#pragma unroll
  for (int o = 16; o > 0; o >>= 1) v += __shfl_xor_sync(0xffffffffu, v, o);
  return v;
}

// ---------- K0: zero the B padding rows ----------
__global__ __launch_bounds__(256) void k0_pad() {
  int i = blockIdx.x * 256 + threadIdx.x;
  if (i < (NPPAD - NP) * NTOP) {
    g_Bh[NP * NTOP + i] = __float2bfloat16(0.f);
    g_Bl[NP * NTOP + i] = __float2bfloat16(0.f);
    if (i < NPPAD - NP) g_svrv[NP + i] = make_float2(0.f, 1.f);
  }
}

// ---------- warp-per-row fused sample + double transform ----------
__device__ __forceinline__ void row_transform(const float* x, float sx, int row,
                                              __nv_bfloat16* Bh, __nv_bfloat16* Bl,
                                              float2* svrv, float* su, float* ru,
                                              int lane, int is_batch) {
  float s1 = 1.f + sqrtf(1.f + sx);
  float sy = sx / (s1 * s1);
  float s2 = 1.f + sqrtf(1.f + sy);
  float scale = 1.f / (s1 * s2);
#pragma unroll
  for (int k = 0; k < 8; k++) {
    float p = x[k] * scale;
    __nv_bfloat16 hi = __float2bfloat16_rn(p);
    int col = k * 32 + lane;
    Bh[row * NTOP + col] = hi;
    Bl[row * NTOP + col] = __float2bfloat16_rn(p - __bfloat162float(hi));
  }
  if (lane == 0) {
    float sp = sy / (s2 * s2);
    float sv = fminf(fmaxf(sp, 0.f), 1.f - 1e-5f);
    float rv = 1.f / (1.f - sv);
    if (is_batch) { su[row] = sv; ru[row] = rv; }
    else svrv[row] = make_float2(sv, rv);
  }
}

__global__ __launch_bounds__(256) void kA(const float* __restrict__ mu,
                                          const float* __restrict__ lv,
                                          unsigned kx0, unsigned kx1) {
  int w = threadIdx.x >> 5, lane = threadIdx.x & 31;
  int r = blockIdx.x * 8 + w;
  int r2 = r + 25000;
  float x1[8], x2[8];
  float sx1 = 0.f, sx2 = 0.f, kl = 0.f;
#pragma unroll
  for (int k = 0; k < 8; k++) {
    int g = r * NTOP + k * 32 + lane;
    unsigned b0, b1;
    tf2x32(kx0, kx1, (unsigned)g, (unsigned)(g + HALF_X), b0, b1);
    float m1 = mu[g], l1 = lv[g];
    x1[k] = fmaf(bits_to_normal(b0), expf(0.5f * l1), m1);
    kl += 1.0f + l1 - m1 * m1 - expf(l1);
    int g2 = g + HALF_X;
    float m2 = mu[g2], l2 = lv[g2];
    x2[k] = fmaf(bits_to_normal(b1), expf(0.5f * l2), m2);
    kl += 1.0f + l2 - m2 * m2 - expf(l2);
    sx1 += x1[k] * x1[k];
    sx2 += x2[k] * x2[k];
  }
  sx1 = wred(sx1); sx2 = wred(sx2); kl = wred(kl);
  row_transform(x1, sx1, r,  g_Bh, g_Bl, g_svrv, 0, 0, lane, 0);
  row_transform(x2, sx2, r2, g_Bh, g_Bl, g_svrv, 0, 0, lane, 0);
  if (lane == 0) g_rp[r] = kl;
}

__global__ __launch_bounds__(256) void kB(const float* __restrict__ mu,
                                          const float* __restrict__ lv,
                                          const int* __restrict__ iidx,
                                          unsigned ki0, unsigned ki1) {
  int w = threadIdx.x >> 5, lane = threadIdx.x & 31;
  int r = blockIdx.x * 8 + w;
  int r2 = r + 512;
  int i1 = iidx[r], i2 = iidx[r2];
  float x1[8], x2[8];
  float sx1 = 0.f, sx2 = 0.f;
#pragma unroll
  for (int k = 0; k < 8; k++) {
    int col = k * 32 + lane;
    int f = r * NTOP + col;
    unsigned b0, b1;
    tf2x32(ki0, ki1, (unsigned)f, (unsigned)(f + HALF_I), b0, b1);
    int a0 = i1 * NTOP + col, a1 = i2 * NTOP + col;
    x1[k] = fmaf(bits_to_normal(b0), expf(0.5f * lv[a0]), mu[a0]);
    x2[k] = fmaf(bits_to_normal(b1), expf(0.5f * lv[a1]), mu[a1]);
    sx1 += x1[k] * x1[k];
    sx2 += x2[k] * x2[k];
  }
  sx1 = wred(sx1); sx2 = wred(sx2);
  row_transform(x1, sx1, r,  g_Ah, g_Al, 0, g_su, g_ru, lane, 1);
  row_transform(x2, sx2, r2, g_Ah, g_Al, 0, g_su, g_ru, lane, 1);
}

// ---------- K5: persistent mma.sync bf16x3 GEMM + fused exp(d) epilogue ----------
__global__ __launch_bounds__(256, 1) void k5_gemm() {
  extern __shared__ char smc[];
  uint32_t sb = smem_u32(smc);
  int t = threadIdx.x, w = t >> 5, lane = t & 31;
  int wm = w & 3, wn = w >> 2;
  int grp = blockIdx.x, b0 = blockIdx.y * 128;
  int ntiles = (NTILES - grp + NG - 1) / NG;

  // per-thread cp.async offsets (precomputed once)
  int tr = t >> 3, li = t & 7;
  uint32_t dstoff[4];
#pragma unroll
  for (int q = 0; q < 4; q++)
    dstoff[q] = SWZ128((uint32_t)((q * 32 + tr) * 128 + li * 16));
  uint32_t soff = (uint32_t)(tr * 512 + li * 16);
  const char* bhp = (const char*)g_Bh;
  const char* blp = (const char*)g_Bl;

  float sub[4], rub2[4];
#pragma unroll
  for (int i = 0; i < 4; i++) {
    int row = b0 + wm * 32 + (i >> 1) * 16 + (lane >> 2) + (i & 1) * 8;
    sub[i] = g_su[row];
    rub2[i] = 2.f * g_ru[row];
  }

  // startup: resident A (4 chunks x hi/lo), B chunk0 of first tile, svrv
#pragma unroll
  for (int c = 0; c < 4; c++) {
#pragma unroll
    for (int q = 0; q < 4; q++) {
      uint32_t so = (uint32_t)(b0 * 512 + c * 128 + q * 16384) + soff;
      cpa16(sb + SMO_A + c * 32768 +         dstoff[q], (const char*)g_Ah + so);
      cpa16(sb + SMO_A + c * 32768 + 16384 + dstoff[q], (const char*)g_Al + so);
    }
  }
  {
    uint32_t so = (uint32_t)(grp * 128 * 512) + soff;
#pragma unroll
    for (int q = 0; q < 4; q++) {
      cpa16(sb + SMO_B +         dstoff[q], bhp + so + q * 16384);
      cpa16(sb + SMO_B + 16384 + dstoff[q], blp + so + q * 16384);
    }
  }
  if (t < 128) cpa8(sb + SMO_SV + t * 8, &g_svrv[grp * 128 + t]);
  CPCOMMIT();

  // ldmatrix address components (hoisted)
  uint32_t a_base[2], a_xor[2];
#pragma unroll
  for (int mt = 0; mt < 2; mt++) {
    int r = wm * 32 + mt * 16 + (lane & 15);
    a_base[mt] = (uint32_t)(r * 128);
    a_xor[mt] = (uint32_t)(r & 7);
  }
  uint32_t b_base[4], b_xor[4];
#pragma unroll
  for (int q = 0; q < 4; q++) {
    int r = wn * 64 + q * 16 + (lane & 15);
    b_base[q] = (uint32_t)(r * 128);
    b_xor[q] = (uint32_t)(r & 7);
  }
  uint32_t ly = (uint32_t)(lane >> 4);

  unsigned cc = 0;
  for (int ti = 0; ti < ntiles; ti++) {
    int nt = grp + ti * NG;
    float acc[2][8][4];
#pragma unroll
    for (int a = 0; a < 2; a++)
#pragma unroll
      for (int b = 0; b < 8; b++)
#pragma unroll
        for (int e = 0; e < 4; e++) acc[a][b][e] = 0.f;

    for (int c = 0; c < 4; c++, cc++) {
      CPWAIT0();
      __syncthreads();
      bool has_next = (c < 3) || (ti < ntiles - 1);
      if (has_next) {
        int nc = (c + 1) & 3;
        int nrt = (c == 3) ? nt + NG : nt;
        uint32_t bs = sb + SMO_B + ((cc + 1) & 1) * 32768;
        uint32_t so = (uint32_t)(nrt * 128 * 512 + nc * 128) + soff;
#pragma unroll
        for (int q = 0; q < 4; q++) {
          cpa16(bs +         dstoff[q], bhp + so + q * 16384);
          cpa16(bs + 16384 + dstoff[q], blp + so + q * 16384);
        }
        if (c == 3 && t < 128)
          cpa8(sb + SMO_SV + ((ti + 1) & 1) * 1024 + t * 8, &g_svrv[nrt * 128 + t]);
        CPCOMMIT();
      }

      uint32_t ab = sb + SMO_A + c * 32768;
      uint32_t bb = sb + SMO_B + (cc & 1) * 32768;
#pragma unroll
      for (int ks = 0; ks < 4; ks++) {
        uint32_t kg = (uint32_t)(ks * 2) + ly;
        // ---- load ALL fragments for this k16 step first ----
        uint32_t aH[2][4], aL[2][4], bH[4][4], bL[4][4];
#pragma unroll
        for (int mt = 0; mt < 2; mt++) {
          uint32_t ad = ab + a_base[mt] + ((kg ^ a_xor[mt]) << 4);
          LDSM4(aH[mt], ad);
          LDSM4(aL[mt], ad + 16384);
        }
#pragma unroll
        for (int q = 0; q < 4; q++) {
          uint32_t bd = bb + b_base[q] + ((kg ^ b_xor[q]) << 4);
          LDSM4(bH[q], bd);
          LDSM4(bL[q], bd + 16384);
        }
        // ---- pass-major MMA: 16 independent accs per pass, reuse distance 16 ----
#pragma unroll
        for (int q = 0; q < 4; q++)
#pragma unroll
          for (int mt = 0; mt < 2; mt++) {
            MMA16816(acc[mt][2 * q],     aH[mt], bH[q][0], bH[q][2]);
            MMA16816(acc[mt][2 * q + 1], aH[mt], bH[q][1], bH[q][3]);
          }
#pragma unroll
        for (int q = 0; q < 4; q++)
#pragma unroll
          for (int mt = 0; mt < 2; mt++) {
            MMA16816(acc[mt][2 * q],     aL[mt], bH[q][0], bH[q][2]);
            MMA16816(acc[mt][2 * q + 1], aL[mt], bH[q][1], bH[q][3]);
          }
#pragma unroll
        for (int q = 0; q < 4; q++)
#pragma unroll
          for (int mt = 0; mt < 2; mt++) {
            MMA16816(acc[mt][2 * q],     aH[mt], bL[q][0], bL[q][2]);
            MMA16816(acc[mt][2 * q + 1], aH[mt], bL[q][1], bL[q][3]);
          }
      }
    }

    // epilogue: e = x + sqrt(x^2-1) from register accumulators
    const float2* svp = (const float2*)(smc + SMO_SV + (ti & 1) * 1024);
    int limit = NP - nt * 128;
    float rs[4] = {0.f, 0.f, 0.f, 0.f};
#pragma unroll
    for (int mt = 0; mt < 2; mt++)
#pragma unroll
      for (int q = 0; q < 8; q++)
#pragma unroll
        for (int e = 0; e < 4; e++) {
          int nl = wn * 64 + q * 8 + 2 * (lane & 3) + (e & 1);
          if (nl < limit) {
            float2 sr = svp[nl];
            int ri = mt * 2 + (e >> 1);
            float qd = fmaxf(fmaf(acc[mt][q][e], -2.f, sub[ri] + sr.x), 0.f);
            float xx = fmaxf(fmaf(qd, rub2[ri] * sr.y, 1.f), 1.0f + 1e-7f);
            float s;
            asm("sqrt.approx.f32 %0, %1;" : "=f"(s) : "f"(fmaf(xx, xx, -1.f)));
            rs[ri] += xx + s;
          }
        }
    float* red = (float*)(smc + SMO_RED);
#pragma unroll
    for (int i = 0; i < 4; i++) {
      rs[i] += __shfl_xor_sync(0xffffffffu, rs[i], 1);
      rs[i] += __shfl_xor_sync(0xffffffffu, rs[i], 2);
      if ((lane & 3) == 0) {
        int row = wm * 32 + (i >> 1) * 16 + (lane >> 2) + (i & 1) * 8;
        red[row * 2 + wn] = rs[i];
      }
    }
    __syncthreads();
    if (t < 128)
      g_partial[(b0 + t) * NTILES + nt] = red[t * 2] + red[t * 2 + 1];
    __syncthreads();
  }
}

// ---------- tails ----------
__global__ void k7_dj(const int* __restrict__ jidx) {
  int b = blockIdx.x, lane = threadIdx.x;
  int jb = jidx[b];
  float dot = 0.f;
  for (int k = lane; k < NTOP; k += 32) {
    float a = __bfloat162float(g_Ah[b * NTOP + k]) + __bfloat162float(g_Al[b * NTOP + k]);
    float v = __bfloat162float(g_Bh[jb * NTOP + k]) + __bfloat162float(g_Bl[jb * NTOP + k]);
    dot += a * v;
  }
#pragma unroll
  for (int o = 16; o > 0; o >>= 1) dot += __shfl_down_sync(0xffffffffu, dot, o);
  if (lane == 0) {
    float2 sr = g_svrv[jb];
    float sq = fmaxf(g_su[b] + sr.x - 2.f * dot, 0.f);
    float xx = fmaxf(fmaf(2.f * sq, g_ru[b] * sr.y, 1.f), 1.0f + 1e-7f);
    g_dj[b] = logf(xx + sqrtf(fmaf(xx, xx, -1.f)));
  }
}

__global__ __launch_bounds__(256) void k6_lse(const float* __restrict__ pij) {
  int b = blockIdx.x, t = threadIdx.x;
  float s = 0.f;
  for (int q = t; q < NTILES; q += 256) s += g_partial[b * NTILES + q];
  __shared__ float sh[256];
  sh[t] = s; __syncthreads();
  for (int w = 128; w > 0; w >>= 1) { if (t < w) sh[t] += sh[t + w]; __syncthreads(); }
  if (t == 0) {
    float pb = pij[b];
    g_kldb[b] = pb * (logf(pb) - (g_dj[b] - logf(sh[0])));
  }
}

__global__ __launch_bounds__(256) void k8_final(float* __restrict__ out) {
  int t = threadIdx.x;
  __shared__ double shd[256];
  double s1 = 0.0, s2 = 0.0;
  for (int b = t; b < BATCH; b += 256) s1 += (double)g_kldb[b];
  for (int q = t; q < KLB; q += 256) s2 += (double)g_rp[q];
  shd[t] = s1; __syncthreads();
  for (int w = 128; w > 0; w >>= 1) { if (t < w) shd[t] += shd[t + w]; __syncthreads(); }
  double kldsum = shd[0]; __syncthreads();
  shd[t] = s2; __syncthreads();
  for (int w = 128; w > 0; w >>= 1) { if (t < w) shd[t] += shd[t + w]; __syncthreads(); }
  if (t == 0)
    out[0] = (float)(kldsum + (-0.5 * shd[0]) * (1024.0 / (50000.0 * 50000.0)));
}

extern "C" void kernel_launch(void* const* d_in, const int* in_sizes, int n_in,
                              void* d_out, int out_size) {
  const float* pij = (const float*)d_in[0];
  const float* mu  = (const float*)d_in[1];
  const float* lv  = (const float*)d_in[2];
  const int*   ii  = (const int*)d_in[3];
  const int*   jj  = (const int*)d_in[4];
  float* out = (float*)d_out;

  unsigned A0, B0, A1, B1;
  tf2x32(0u, 42u, 0u, 2u, A0, B0);   // kx
  tf2x32(0u, 42u, 1u, 3u, A1, B1);   // ki

  cudaFuncSetAttribute(k5_gemm, cudaFuncAttributeMaxDynamicSharedMemorySize, SMT_TOT);

  k0_pad<<<48, 256>>>();
  kA<<<3125, 256>>>(mu, lv, A0, A1);
  kB<<<64, 256>>>(mu, lv, ii, B0, B1);
  k5_gemm<<<dim3(NG, 8), 256, SMT_TOT>>>();
  k7_dj<<<BATCH, 32>>>(jj);
  k6_lse<<<BATCH, 256>>>(pij);
  k8_final<<<1, 256>>>(out);
}

// round 8
// speedup vs baseline: 2.3765x; 1.1324x over previous
#include <cuda_runtime.h>
#include <cuda_bf16.h>
#include <cstdint>

#define NP 50000
#define NPPAD 50048
#define NTOP 256
#define BATCH 1024
#define HALF_X 6400000
#define HALF_I 131072
#define KLB 25000
#define NTILES 391
#define NG 18

// dynamic smem layout (byte offsets)
#define SMO_A   0         // 4 chunks x {Ah,Al} x 16KB = 128KB
#define SMO_B   131072    // 2 stages x {Bh,Bl} x 16KB = 64KB
#define SMO_SV  196608    // 2 x 128 float2 = 2KB
#define SMO_RED 198656    // 128 x 4 float = 2KB
#define SMT_TOT 200704

__device__ __align__(256) __nv_bfloat16 g_Bh[NPPAD * NTOP];
__device__ __align__(256) __nv_bfloat16 g_Bl[NPPAD * NTOP];
__device__ __align__(256) __nv_bfloat16 g_Ah[BATCH * NTOP];
__device__ __align__(256) __nv_bfloat16 g_Al[BATCH * NTOP];
__device__ float2 g_svrv[NPPAD];
__device__ float g_su[BATCH], g_ru[BATCH];
__device__ float g_partial[BATCH * NTILES];
__device__ float g_dj[BATCH], g_kldb[BATCH], g_rp[KLB];

// ---------- PTX helpers (plain sm_100-legal) ----------
__device__ __forceinline__ uint32_t smem_u32(const void* p) {
  uint32_t a;
  asm("{ .reg .u64 t; cvta.to.shared.u64 t, %1; cvt.u32.u64 %0, t; }" : "=r"(a) : "l"(p));
  return a;
}
#define SWZ128(o) ((o) ^ (((o) >> 3) & 0x70))
__device__ __forceinline__ void cpa16(uint32_t d, const void* s) {
  asm volatile("cp.async.cg.shared.global [%0], [%1], 16;" :: "r"(d), "l"(s));
}
__device__ __forceinline__ void cpa8(uint32_t d, const void* s) {
  asm volatile("cp.async.ca.shared.global [%0], [%1], 8;" :: "r"(d), "l"(s));
}
#define CPCOMMIT() asm volatile("cp.async.commit_group;" ::: "memory")
#define CPWAIT0()  asm volatile("cp.async.wait_group 0;" ::: "memory")

#define LDSM4(r, addr) \
  asm volatile("ldmatrix.sync.aligned.m8n8.x4.shared.b16 {%0,%1,%2,%3}, [%4];" \
    : "=r"((r)[0]), "=r"((r)[1]), "=r"((r)[2]), "=r"((r)[3]) : "r"(addr))

#define MMA16816(d, a, b0r, b1r) \
  asm volatile("mma.sync.aligned.m16n8k16.row.col.f32.bf16.bf16.f32 " \
    "{%0,%1,%2,%3}, {%4,%5,%6,%7}, {%8,%9}, {%0,%1,%2,%3};" \
    : "+f"((d)[0]), "+f"((d)[1]), "+f"((d)[2]), "+f"((d)[3]) \
    : "r"((a)[0]), "r"((a)[1]), "r"((a)[2]), "r"((a)[3]), "r"(b0r), "r"(b1r))

// ---------- Threefry-2x32 (exact JAX) ----------
__host__ __device__ __forceinline__ void tf2x32(unsigned k0, unsigned k1,
                                                unsigned c0, unsigned c1,
                                                unsigned& o0, unsigned& o1) {
  unsigned ks2 = k0 ^ k1 ^ 0x1BD11BDAu;
  unsigned x0 = c0 + k0, x1 = c1 + k1;
#define TF_R(d) { x0 += x1; x1 = (x1 << (d)) | (x1 >> (32 - (d))); x1 ^= x0; }
  TF_R(13) TF_R(15) TF_R(26) TF_R(6)   x0 += k1;  x1 += ks2 + 1u;
  TF_R(17) TF_R(29) TF_R(16) TF_R(24)  x0 += ks2; x1 += k0 + 2u;
  TF_R(13) TF_R(15) TF_R(26) TF_R(6)   x0 += k0;  x1 += k1 + 3u;
  TF_R(17) TF_R(29) TF_R(16) TF_R(24)  x0 += k1;  x1 += ks2 + 4u;
  TF_R(13) TF_R(15) TF_R(26) TF_R(6)   x0 += ks2; x1 += k0 + 5u;
#undef TF_R
  o0 = x0; o1 = x1;
}
__device__ __forceinline__ float bits_to_normal(unsigned bits) {
  float f = __uint_as_float((bits >> 9) | 0x3f800000u) - 1.0f;
  float lo = __uint_as_float(0xBF7FFFFFu);
  return 1.41421356237f * erfinvf(fmaxf(lo, fmaf(f, 2.0f, lo)));
}
__device__ __forceinline__ float wred(float v) {
#pragma unroll
  for (int o = 16; o > 0; o >>= 1) v += __shfl_xor_sync(0xffffffffu, v, o);
  return v;
}

// ---------- K0: zero the B padding rows ----------
__global__ __launch_bounds__(256) void k0_pad() {
  int i = blockIdx.x * 256 + threadIdx.x;
  if (i < (NPPAD - NP) * NTOP) {
    g_Bh[NP * NTOP + i] = __float2bfloat16(0.f);
    g_Bl[NP * NTOP + i] = __float2bfloat16(0.f);
    if (i < NPPAD - NP) g_svrv[NP + i] = make_float2(0.f, 1.f);
  }
}

// ---------- warp-per-row fused sample + double transform ----------
__device__ __forceinline__ void row_transform(const float* x, float sx, int row,
                                              __nv_bfloat16* Bh, __nv_bfloat16* Bl,
                                              float2* svrv, float* su, float* ru,
                                              int lane, int is_batch) {
  float s1 = 1.f + sqrtf(1.f + sx);
  float sy = sx / (s1 * s1);
  float s2 = 1.f + sqrtf(1.f + sy);
  float scale = 1.f / (s1 * s2);
#pragma unroll
  for (int k = 0; k < 8; k++) {
    float p = x[k] * scale;
    __nv_bfloat16 hi = __float2bfloat16_rn(p);
    int col = k * 32 + lane;
    Bh[row * NTOP + col] = hi;
    Bl[row * NTOP + col] = __float2bfloat16_rn(p - __bfloat162float(hi));
  }
  if (lane == 0) {
    float sp = sy / (s2 * s2);
    float sv = fminf(fmaxf(sp, 0.f), 1.f - 1e-5f);
    float rv = 1.f / (1.f - sv);
    if (is_batch) { su[row] = sv; ru[row] = rv; }
    else svrv[row] = make_float2(sv, rv);
  }
}

__global__ __launch_bounds__(256) void kA(const float* __restrict__ mu,
                                          const float* __restrict__ lv,
                                          unsigned kx0, unsigned kx1) {
  int w = threadIdx.x >> 5, lane = threadIdx.x & 31;
  int r = blockIdx.x * 8 + w;
  int r2 = r + 25000;
  float x1[8], x2[8];
  float sx1 = 0.f, sx2 = 0.f, kl = 0.f;
#pragma unroll
  for (int k = 0; k < 8; k++) {
    int g = r * NTOP + k * 32 + lane;
    unsigned b0, b1;
    tf2x32(kx0, kx1, (unsigned)g, (unsigned)(g + HALF_X), b0, b1);
    float m1 = mu[g], l1 = lv[g];
    x1[k] = fmaf(bits_to_normal(b0), expf(0.5f * l1), m1);
    kl += 1.0f + l1 - m1 * m1 - expf(l1);
    int g2 = g + HALF_X;
    float m2 = mu[g2], l2 = lv[g2];
    x2[k] = fmaf(bits_to_normal(b1), expf(0.5f * l2), m2);
    kl += 1.0f + l2 - m2 * m2 - expf(l2);
    sx1 += x1[k] * x1[k];
    sx2 += x2[k] * x2[k];
  }
  sx1 = wred(sx1); sx2 = wred(sx2); kl = wred(kl);
  row_transform(x1, sx1, r,  g_Bh, g_Bl, g_svrv, 0, 0, lane, 0);
  row_transform(x2, sx2, r2, g_Bh, g_Bl, g_svrv, 0, 0, lane, 0);
  if (lane == 0) g_rp[r] = kl;
}

__global__ __launch_bounds__(256) void kB(const float* __restrict__ mu,
                                          const float* __restrict__ lv,
                                          const int* __restrict__ iidx,
                                          unsigned ki0, unsigned ki1) {
  int w = threadIdx.x >> 5, lane = threadIdx.x & 31;
  int r = blockIdx.x * 8 + w;
  int r2 = r + 512;
  int i1 = iidx[r], i2 = iidx[r2];
  float x1[8], x2[8];
  float sx1 = 0.f, sx2 = 0.f;
#pragma unroll
  for (int k = 0; k < 8; k++) {
    int col = k * 32 + lane;
    int f = r * NTOP + col;
    unsigned b0, b1;
    tf2x32(ki0, ki1, (unsigned)f, (unsigned)(f + HALF_I), b0, b1);
    int a0 = i1 * NTOP + col, a1 = i2 * NTOP + col;
    x1[k] = fmaf(bits_to_normal(b0), expf(0.5f * lv[a0]), mu[a0]);
    x2[k] = fmaf(bits_to_normal(b1), expf(0.5f * lv[a1]), mu[a1]);
    sx1 += x1[k] * x1[k];
    sx2 += x2[k] * x2[k];
  }
  sx1 = wred(sx1); sx2 = wred(sx2);
  row_transform(x1, sx1, r,  g_Ah, g_Al, 0, g_su, g_ru, lane, 1);
  row_transform(x2, sx2, r2, g_Ah, g_Al, 0, g_su, g_ru, lane, 1);
}

// ---------- K5: persistent mma.sync bf16x3 GEMM, 16 warps, fused epilogue ----------
// 512 threads: warp w covers rows wm*32..+32 (wm=w&3), cols wn*32..+32 (wn=w>>2).
__global__ __launch_bounds__(512, 1) void k5_gemm() {
  extern __shared__ char smc[];
  uint32_t sb = smem_u32(smc);
  int t = threadIdx.x, w = t >> 5, lane = t & 31;
  int wm = w & 3, wn = w >> 2;     // wn in 0..3
  int grp = blockIdx.x, b0 = blockIdx.y * 128;
  int ntiles = (NTILES - grp + NG - 1) / NG;

  // per-thread cp.async offsets: 512 threads cover a 16KB tile in 2 rounds
  int tr = t >> 3, li = t & 7;     // tr 0..63, li 0..7
  uint32_t dstoff[2];
#pragma unroll
  for (int q = 0; q < 2; q++)
    dstoff[q] = SWZ128((uint32_t)((q * 64 + tr) * 128 + li * 16));
  uint32_t soff = (uint32_t)(tr * 512 + li * 16);
  const char* bhp = (const char*)g_Bh;
  const char* blp = (const char*)g_Bl;

  float sub[4], rub2[4];
#pragma unroll
  for (int i = 0; i < 4; i++) {
    int row = b0 + wm * 32 + (i >> 1) * 16 + (lane >> 2) + (i & 1) * 8;
    sub[i] = g_su[row];
    rub2[i] = 2.f * g_ru[row];
  }

  // startup: resident A (4 chunks x hi/lo), B chunk0 of first tile, svrv
#pragma unroll
  for (int c = 0; c < 4; c++) {
#pragma unroll
    for (int q = 0; q < 2; q++) {
      uint32_t so = (uint32_t)(b0 * 512 + c * 128 + q * 32768) + soff;
      cpa16(sb + SMO_A + c * 32768 +         dstoff[q], (const char*)g_Ah + so);
      cpa16(sb + SMO_A + c * 32768 + 16384 + dstoff[q], (const char*)g_Al + so);
    }
  }
  {
    uint32_t so = (uint32_t)(grp * 128 * 512) + soff;
#pragma unroll
    for (int q = 0; q < 2; q++) {
      cpa16(sb + SMO_B +         dstoff[q], bhp + so + q * 32768);
      cpa16(sb + SMO_B + 16384 + dstoff[q], blp + so + q * 32768);
    }
  }
  if (t < 128) cpa8(sb + SMO_SV + t * 8, &g_svrv[grp * 128 + t]);
  CPCOMMIT();

  // ldmatrix address components (hoisted)
  uint32_t a_base[2], a_xor[2];
#pragma unroll
  for (int mt = 0; mt < 2; mt++) {
    int r = wm * 32 + mt * 16 + (lane & 15);
    a_base[mt] = (uint32_t)(r * 128);
    a_xor[mt] = (uint32_t)(r & 7);
  }
  uint32_t b_base[2], b_xor[2];
#pragma unroll
  for (int q = 0; q < 2; q++) {
    int r = wn * 32 + q * 16 + (lane & 15);
    b_base[q] = (uint32_t)(r * 128);
    b_xor[q] = (uint32_t)(r & 7);
  }
  uint32_t ly = (uint32_t)(lane >> 4);

  unsigned cc = 0;
  for (int ti = 0; ti < ntiles; ti++) {
    int nt = grp + ti * NG;
    float acc[2][4][4];
#pragma unroll
    for (int a = 0; a < 2; a++)
#pragma unroll
      for (int b = 0; b < 4; b++)
#pragma unroll
        for (int e = 0; e < 4; e++) acc[a][b][e] = 0.f;

    for (int c = 0; c < 4; c++, cc++) {
      CPWAIT0();
      __syncthreads();
      bool has_next = (c < 3) || (ti < ntiles - 1);
      if (has_next) {
        int nc = (c + 1) & 3;
        int nrt = (c == 3) ? nt + NG : nt;
        uint32_t bs = sb + SMO_B + ((cc + 1) & 1) * 32768;
        uint32_t so = (uint32_t)(nrt * 128 * 512 + nc * 128) + soff;
#pragma unroll
        for (int q = 0; q < 2; q++) {
          cpa16(bs +         dstoff[q], bhp + so + q * 32768);
          cpa16(bs + 16384 + dstoff[q], blp + so + q * 32768);
        }
        if (c == 3 && t < 128)
          cpa8(sb + SMO_SV + ((ti + 1) & 1) * 1024 + t * 8, &g_svrv[nrt * 128 + t]);
        CPCOMMIT();
      }

      uint32_t ab = sb + SMO_A + c * 32768;
      uint32_t bb = sb + SMO_B + (cc & 1) * 32768;
#pragma unroll
      for (int ks = 0; ks < 4; ks++) {
        uint32_t kg = (uint32_t)(ks * 2) + ly;
        uint32_t aH[2][4], aL[2][4], bH[2][4], bL[2][4];
#pragma unroll
        for (int mt = 0; mt < 2; mt++) {
          uint32_t ad = ab + a_base[mt] + ((kg ^ a_xor[mt]) << 4);
          LDSM4(aH[mt], ad);
          LDSM4(aL[mt], ad + 16384);
        }
#pragma unroll
        for (int q = 0; q < 2; q++) {
          uint32_t bd = bb + b_base[q] + ((kg ^ b_xor[q]) << 4);
          LDSM4(bH[q], bd);
          LDSM4(bL[q], bd + 16384);
        }
        // pass-major: 8 independent accumulators per pass
#pragma unroll
        for (int q = 0; q < 2; q++)
#pragma unroll
          for (int mt = 0; mt < 2; mt++) {
            MMA16816(acc[mt][2 * q],     aH[mt], bH[q][0], bH[q][2]);
            MMA16816(acc[mt][2 * q + 1], aH[mt], bH[q][1], bH[q][3]);
          }
#pragma unroll
        for (int q = 0; q < 2; q++)
#pragma unroll
          for (int mt = 0; mt < 2; mt++) {
            MMA16816(acc[mt][2 * q],     aL[mt], bH[q][0], bH[q][2]);
            MMA16816(acc[mt][2 * q + 1], aL[mt], bH[q][1], bH[q][3]);
          }
#pragma unroll
        for (int q = 0; q < 2; q++)
#pragma unroll
          for (int mt = 0; mt < 2; mt++) {
            MMA16816(acc[mt][2 * q],     aH[mt], bL[q][0], bL[q][2]);
            MMA16816(acc[mt][2 * q + 1], aH[mt], bL[q][1], bL[q][3]);
          }
      }
    }

    // epilogue: e = x + sqrt(x^2-1) from register accumulators
    const float2* svp = (const float2*)(smc + SMO_SV + (ti & 1) * 1024);
    int limit = NP - nt * 128;
    float rs[4] = {0.f, 0.f, 0.f, 0.f};
#pragma unroll
    for (int mt = 0; mt < 2; mt++)
#pragma unroll
      for (int q = 0; q < 4; q++)
#pragma unroll
        for (int e = 0; e < 4; e++) {
          int nl = wn * 32 + q * 8 + 2 * (lane & 3) + (e & 1);
          if (nl < limit) {
            float2 sr = svp[nl];
            int ri = mt * 2 + (e >> 1);
            float qd = fmaxf(fmaf(acc[mt][q][e], -2.f, sub[ri] + sr.x), 0.f);
            float xx = fmaxf(fmaf(qd, rub2[ri] * sr.y, 1.f), 1.0f + 1e-7f);
            float s;
            asm("sqrt.approx.f32 %0, %1;" : "=f"(s) : "f"(fmaf(xx, xx, -1.f)));
            rs[ri] += xx + s;
          }
        }
    float* red = (float*)(smc + SMO_RED);
#pragma unroll
    for (int i = 0; i < 4; i++) {
      rs[i] += __shfl_xor_sync(0xffffffffu, rs[i], 1);
      rs[i] += __shfl_xor_sync(0xffffffffu, rs[i], 2);
      if ((lane & 3) == 0) {
        int row = wm * 32 + (i >> 1) * 16 + (lane >> 2) + (i & 1) * 8;
        red[row * 4 + wn] = rs[i];
      }
    }
    __syncthreads();
    if (t < 128)
      g_partial[(b0 + t) * NTILES + nt] =
          (red[t * 4] + red[t * 4 + 1]) + (red[t * 4 + 2] + red[t * 4 + 3]);
    __syncthreads();
  }
}

// ---------- tails ----------
__global__ void k7_dj(const int* __restrict__ jidx) {
  int b = blockIdx.x, lane = threadIdx.x;
  int jb = jidx[b];
  float dot = 0.f;
  for (int k = lane; k < NTOP; k += 32) {
    float a = __bfloat162float(g_Ah[b * NTOP + k]) + __bfloat162float(g_Al[b * NTOP + k]);
    float v = __bfloat162float(g_Bh[jb * NTOP + k]) + __bfloat162float(g_Bl[jb * NTOP + k]);
    dot += a * v;
  }
#pragma unroll
  for (int o = 16; o > 0; o >>= 1) dot += __shfl_down_sync(0xffffffffu, dot, o);
  if (lane == 0) {
    float2 sr = g_svrv[jb];
    float sq = fmaxf(g_su[b] + sr.x - 2.f * dot, 0.f);
    float xx = fmaxf(fmaf(2.f * sq, g_ru[b] * sr.y, 1.f), 1.0f + 1e-7f);
    g_dj[b] = logf(xx + sqrtf(fmaf(xx, xx, -1.f)));
  }
}

__global__ __launch_bounds__(256) void k6_lse(const float* __restrict__ pij) {
  int b = blockIdx.x, t = threadIdx.x;
  float s = 0.f;
  for (int q = t; q < NTILES; q += 256) s += g_partial[b * NTILES + q];
  __shared__ float sh[256];
  sh[t] = s; __syncthreads();
  for (int w = 128; w > 0; w >>= 1) { if (t < w) sh[t] += sh[t + w]; __syncthreads(); }
  if (t == 0) {
    float pb = pij[b];
    g_kldb[b] = pb * (logf(pb) - (g_dj[b] - logf(sh[0])));
  }
}

__global__ __launch_bounds__(256) void k8_final(float* __restrict__ out) {
  int t = threadIdx.x;
  __shared__ double shd[256];
  double s1 = 0.0, s2 = 0.0;
  for (int b = t; b < BATCH; b += 256) s1 += (double)g_kldb[b];
  for (int q = t; q < KLB; q += 256) s2 += (double)g_rp[q];
  shd[t] = s1; __syncthreads();
  for (int w = 128; w > 0; w >>= 1) { if (t < w) shd[t] += shd[t + w]; __syncthreads(); }
  double kldsum = shd[0]; __syncthreads();
  shd[t] = s2; __syncthreads();
  for (int w = 128; w > 0; w >>= 1) { if (t < w) shd[t] += shd[t + w]; __syncthreads(); }
  if (t == 0)
    out[0] = (float)(kldsum + (-0.5 * shd[0]) * (1024.0 / (50000.0 * 50000.0)));
}

extern "C" void kernel_launch(void* const* d_in, const int* in_sizes, int n_in,
                              void* d_out, int out_size) {
  const float* pij = (const float*)d_in[0];
  const float* mu  = (const float*)d_in[1];
  const float* lv  = (const float*)d_in[2];
  const int*   ii  = (const int*)d_in[3];
  const int*   jj  = (const int*)d_in[4];
  float* out = (float*)d_out;

  unsigned A0, B0, A1, B1;
  tf2x32(0u, 42u, 0u, 2u, A0, B0);   // kx
  tf2x32(0u, 42u, 1u, 3u, A1, B1);   // ki

  cudaFuncSetAttribute(k5_gemm, cudaFuncAttributeMaxDynamicSharedMemorySize, SMT_TOT);

  k0_pad<<<48, 256>>>();
  kA<<<3125, 256>>>(mu, lv, A0, A1);
  kB<<<64, 256>>>(mu, lv, ii, B0, B1);
  k5_gemm<<<dim3(NG, 8), 512, SMT_TOT>>>();
  k7_dj<<<BATCH, 32>>>(jj);
  k6_lse<<<BATCH, 256>>>(pij);
  k8_final<<<1, 256>>>(out);
}